// round 4
// baseline (speedup 1.0000x reference)
#include <cuda_runtime.h>

#define N_NODES 50000
#define N_EDGES 1000000
#define TABLE_SIZE 32768

#define NODE_BLOCKS ((N_NODES + 255) / 256)
#define EDGE_BLOCKS ((N_EDGES + 255) / 256)
#define EDGE_GRID (148 * 8)   // grid-stride persistent-ish edge kernel

// ---------------- persistent scratch (no allocs allowed) ----------------
__device__ __align__(16) float4 g_pos4[N_NODES];        // packed positions
__device__ __align__(16) int2   g_edge[N_EDGES];        // {sender, receiver}
__device__ __align__(16) float4 g_nhat[N_EDGES];        // unit edge vector, .w = length
__device__ __align__(16) float  g_ssc[N_NODES * 3];     // self-connection scalar (layer l)
__device__ __align__(16) float  g_vsc[N_NODES * 6];     // self-connection vector (layer l)
__device__ __align__(16) float  g_usrc[N_NODES * 8];    // packed sender feats {vu[6], su, pad}
__device__ __align__(16) float  g_agg[N_NODES * 20];    // {agg_s[3], agg_v[15], pad[2]}
__device__ __align__(16) float  g_table[3 * TABLE_SIZE * 8]; // mix_l(length) table

__device__ __forceinline__ float swishf(float x) {
    return __fdividef(x, 1.0f + __expf(-x));
}

// ---------------- K_pack: positions -> float4 ----------------
__global__ __launch_bounds__(256) void pack_pos_kernel(const float* __restrict__ pos)
{
    int n = blockIdx.x * 256 + threadIdx.x;
    if (n >= N_NODES) return;
    g_pos4[n] = make_float4(pos[3*n+0], pos[3*n+1], pos[3*n+2], 0.f);
}

// ---------------- K0: edge geometry + packed index (once per replay) ----------------
__global__ __launch_bounds__(256) void geom_kernel(
    const int* __restrict__ senders,
    const int* __restrict__ receivers)
{
    int e = blockIdx.x * 256 + threadIdx.x;
    if (e >= N_EDGES) return;
    int a = senders[e], b = receivers[e];
    g_edge[e] = make_int2(a, b);
    float4 pa = g_pos4[a];
    float4 pb = g_pos4[b];
    float dx = pb.x - pa.x;
    float dy = pb.y - pa.y;
    float dz = pb.z - pa.z;
    float len = sqrtf(dx*dx + dy*dy + dz*dz);
    float inv = (len > 0.f) ? (1.f / len) : 0.f;
    g_nhat[e] = make_float4(dx*inv, dy*inv, dz*inv, len);
}

// ---------------- K_tab: build mix(length) table, all 3 layers ----------------
__global__ __launch_bounds__(128) void table_kernel(
    const float* __restrict__ W1g, const float* __restrict__ W2g,
    const float* __restrict__ W3g)
{
    int l = blockIdx.y;
    const float* W1 = W1g + l * 512;
    const float* W2 = W2g + l * 4096;
    const float* W3 = W3g + l * 512;

    __shared__ float sW1[8*64];
    __shared__ float sW2[64*64];
    __shared__ float sW3[64*8];
    for (int i = threadIdx.x; i < 512; i += 128) { sW1[i] = W1[i]; sW3[i] = W3[i]; }
    for (int i = threadIdx.x; i < 4096; i += 128) sW2[i] = W2[i];
    __syncthreads();

    int idx = blockIdx.x * 128 + threadIdx.x;
    if (idx >= TABLE_SIZE) return;
    float x = (float)idx * (1.0f / (float)(TABLE_SIZE - 1));

    // radial basis at length x
    float x2 = x*x, x3 = x2*x, x6 = x3*x3, x7 = x6*x, x8 = x7*x;
    float poly = 1.f - 28.f*x6 + 48.f*x7 - 21.f*x8;
    float env = (x < 1.f) ? poly : 0.f;
    float inv = (x > 0.f) ? (1.f / x) : 0.f;
    float coef = 1.4142135623730951f * env * inv;
    float th = 3.14159265358979323846f * x;
    float s1, c1;
    sincosf(th, &s1, &c1);
    float c2 = 2.f * c1;
    float skm = 0.f, sk = s1;
    float rad[8];
#pragma unroll
    for (int k = 0; k < 8; ++k) {
        rad[k] = coef * sk;
        float sn = fmaf(c2, sk, -skm);
        skm = sk; sk = sn;
    }
    if (idx == 0) {
#pragma unroll
        for (int k = 0; k < 8; ++k) rad[k] = 0.f;  // len==0 edges skip anyway
    }

    // h = swish(radial @ W1 / sqrt(8))
    float h[64];
#pragma unroll
    for (int j = 0; j < 64; ++j) {
        float acc = 0.f;
#pragma unroll
        for (int i = 0; i < 8; ++i) acc = fmaf(rad[i], sW1[i*64 + j], acc);
        h[j] = swishf(acc * 0.35355339059327373f);
    }

    float mix[8];
#pragma unroll
    for (int k = 0; k < 8; ++k) mix[k] = 0.f;
#pragma unroll 1
    for (int jc = 0; jc < 64; jc += 16) {
        float g[16];
#pragma unroll
        for (int j = 0; j < 16; ++j) g[j] = 0.f;
#pragma unroll
        for (int i = 0; i < 64; ++i) {
            float hi = h[i];
            const float* w = &sW2[i*64 + jc];
#pragma unroll
            for (int j = 0; j < 16; ++j) g[j] = fmaf(hi, w[j], g[j]);
        }
#pragma unroll
        for (int j = 0; j < 16; ++j) {
            float gs = swishf(g[j] * 0.125f);
            const float* w3 = &sW3[(jc + j)*8];
#pragma unroll
            for (int k = 0; k < 8; ++k) mix[k] = fmaf(gs, w3[k], mix[k]);
        }
    }
    float4* T = (float4*)(g_table + ((size_t)l * TABLE_SIZE + idx) * 8);
    T[0] = make_float4(mix[0]*0.125f, mix[1]*0.125f, mix[2]*0.125f, mix[3]*0.125f);
    T[1] = make_float4(mix[4]*0.125f, mix[5]*0.125f, mix[6]*0.125f, mix[7]*0.125f);
}

// ---------------- per-node "pre" body (shared by fused kernels) ----------------
__device__ __forceinline__ void node_pre_body(
    int n, float s, const float* v,
    const float* __restrict__ Wss, const float* __restrict__ Wsv,
    const float* __restrict__ Wus, const float* __restrict__ Wuv)
{
    const float IS2 = 0.7071067811865476f;
#pragma unroll
    for (int j = 0; j < 3; ++j) g_ssc[n*3+j] = s * Wss[j];
#pragma unroll
    for (int k = 0; k < 2; ++k)
#pragma unroll
        for (int c = 0; c < 3; ++c)
            g_vsc[n*6 + k*3 + c] = (v[c]*Wsv[0*2+k] + v[3+c]*Wsv[1*2+k]) * IS2;

    float su = s * Wus[0];
    float vu[6];
#pragma unroll
    for (int k = 0; k < 2; ++k)
#pragma unroll
        for (int c = 0; c < 3; ++c)
            vu[k*3+c] = (v[c]*Wuv[0*2+k] + v[3+c]*Wuv[1*2+k]) * IS2;

    float4* u4 = (float4*)g_usrc;
    u4[2*n+0] = make_float4(vu[0], vu[1], vu[2], vu[3]);
    u4[2*n+1] = make_float4(vu[4], vu[5], su, 0.f);

    float4* ag4 = (float4*)(g_agg + (size_t)n*20);
#pragma unroll
    for (int i = 0; i < 5; ++i) ag4[i] = make_float4(0.f, 0.f, 0.f, 0.f);
}

// ---------------- per-node "post" body: agg+sc -> new (s, v) ----------------
__device__ __forceinline__ void node_post_body(
    int n, const float* __restrict__ Wds, const float* __restrict__ Wdv,
    float& s_out, float* v_out)
{
    const float IS3 = 0.5773502691896258f;
    const float IS5 = 0.4472135954999579f;
    const float* base = g_agg + (size_t)n * 20;
    float as0 = base[0], as1 = base[1], as2 = base[2];
    float av[15];
#pragma unroll
    for (int i = 0; i < 15; ++i) av[i] = base[3 + i];

    float st[3];
#pragma unroll
    for (int j = 0; j < 3; ++j) {
        float sd = (as0*Wds[j] + as1*Wds[3+j] + as2*Wds[6+j]) * IS3;
        st[j] = sd + g_ssc[n*3 + j];
    }
    float vt[6];
#pragma unroll
    for (int k = 0; k < 2; ++k)
#pragma unroll
        for (int c = 0; c < 3; ++c) {
            float vd = 0.f;
#pragma unroll
            for (int m = 0; m < 5; ++m) vd = fmaf(av[m*3 + c], Wdv[m*2 + k], vd);
            vt[k*3 + c] = vd * IS5 + g_vsc[n*6 + k*3 + c];
        }

    s_out = swishf(st[0]);
    float a1 = swishf(st[1]);
    float a2 = swishf(st[2]);
#pragma unroll
    for (int c = 0; c < 3; ++c) {
        v_out[c]     = vt[c]     * a1;
        v_out[3 + c] = vt[3 + c] * a2;
    }
}

// ---------------- K1a: init from node_features + pre(0) ----------------
__global__ __launch_bounds__(256) void node_first_kernel(
    const float* __restrict__ nf,
    const float* __restrict__ Wss, const float* __restrict__ Wsv,
    const float* __restrict__ Wus, const float* __restrict__ Wuv)
{
    int n = blockIdx.x * 256 + threadIdx.x;
    if (n >= N_NODES) return;
    float s = nf[n*7];
    float v[6];
#pragma unroll
    for (int k = 0; k < 6; ++k) v[k] = nf[n*7 + 1 + k];
    node_pre_body(n, s, v, Wss, Wsv, Wus, Wuv);
}

// ---------------- K1b: post(l-1) fused with pre(l) ----------------
__global__ __launch_bounds__(256) void node_fused_kernel(
    const float* __restrict__ Wds, const float* __restrict__ Wdv,  // layer l-1
    const float* __restrict__ Wss, const float* __restrict__ Wsv,  // layer l
    const float* __restrict__ Wus, const float* __restrict__ Wuv)
{
    int n = blockIdx.x * 256 + threadIdx.x;
    if (n >= N_NODES) return;
    float s, v[6];
    node_post_body(n, Wds, Wdv, s, v);
    node_pre_body(n, s, v, Wss, Wsv, Wus, Wuv);   // also zeros agg for layer l
}

// ---------------- K1c: final post (layer 2) -> out ----------------
__global__ __launch_bounds__(256) void node_final_kernel(
    const float* __restrict__ Wds, const float* __restrict__ Wdv,
    float* __restrict__ out)
{
    int n = blockIdx.x * 256 + threadIdx.x;
    if (n >= N_NODES) return;
    float s, v[6];
    node_post_body(n, Wds, Wdv, s, v);
#pragma unroll
    for (int c = 0; c < 3; ++c) out[n*3 + c] = v[c];
}

// ---------------- K2: per-edge table lookup + messages + vector scatter ----------------
__global__ __launch_bounds__(256) void edge_kernel(int layer)
{
    const float4* Tbase = (const float4*)(g_table + (size_t)layer * TABLE_SIZE * 8);
    for (int e = blockIdx.x * 256 + threadIdx.x; e < N_EDGES; e += EDGE_GRID * 256) {
        float4 nh = g_nhat[e];
        float len = nh.w;
        // reference: radial==0 (=> mix==0 => all messages 0) for len==0 or len>=1
        if (len <= 0.f || len >= 1.f) continue;

        // mix(len) via table lerp
        float t = len * (float)(TABLE_SIZE - 1);
        int i0 = (int)t;
        if (i0 > TABLE_SIZE - 2) i0 = TABLE_SIZE - 2;
        float fr = t - (float)i0;
        const float4* T = Tbase + i0 * 2;
        float4 a0 = T[0], a1 = T[1], b0 = T[2], b1 = T[3];
        float m0 = fmaf(fr, b0.x - a0.x, a0.x);
        float m1 = fmaf(fr, b0.y - a0.y, a0.y);
        float m2 = fmaf(fr, b0.z - a0.z, a0.z);
        float m3 = fmaf(fr, b0.w - a0.w, a0.w);
        float m4 = fmaf(fr, b1.x - a1.x, a1.x);
        float m5 = fmaf(fr, b1.y - a1.y, a1.y);
        float m6 = fmaf(fr, b1.z - a1.z, a1.z);
        float m7 = fmaf(fr, b1.w - a1.w, a1.w);

        // gather sender features
        int2 ed = g_edge[e];
        int snd = ed.x, rcv = ed.y;
        const float4* u4 = (const float4*)g_usrc;
        float4 u0 = u4[2*snd+0], u1 = u4[2*snd+1];
        float v00 = u0.x, v01 = u0.y, v02 = u0.z;
        float v10 = u0.w, v11 = u1.x, v12 = u1.y;
        float se  = u1.z;
        float nx = nh.x, ny = nh.y, nz = nh.z;
        float vd0 = v00*nx + v01*ny + v02*nz;
        float vd1 = v10*nx + v11*ny + v12*nz;

        const float THIRD = 0.3333333333333333f;
        float f5 = 2.1213203435596424f * m5;
        float f6 = 2.1213203435596424f * m6;
        float f7 = 1.7320508075688772f * se * m7;

        float* base = g_agg + (size_t)rcv * 20;
        // layout: [as0 as1 as2 | r0.xyz r1.xyz | pc0.xyz pc1.xyz | pb.xyz]
        atomicAdd((float4*)(base + 0),
                  make_float4(se*m0, vd0*m1, vd1*m2, v00*m3));
        atomicAdd((float4*)(base + 4),
                  make_float4(v01*m3, v02*m3, v10*m4, v11*m4));
        atomicAdd((float4*)(base + 8),
                  make_float4(v12*m4,
                              f5 * (vd0*nx - v00*THIRD),
                              f5 * (vd0*ny - v01*THIRD),
                              f5 * (vd0*nz - v02*THIRD)));
        atomicAdd((float4*)(base + 12),
                  make_float4(f6 * (vd1*nx - v10*THIRD),
                              f6 * (vd1*ny - v11*THIRD),
                              f6 * (vd1*nz - v12*THIRD),
                              f7 * nx));
        atomicAdd((float2*)(base + 16), make_float2(f7 * ny, f7 * nz));
    }
}

// ---------------- launch ----------------
extern "C" void kernel_launch(void* const* d_in, const int* in_sizes, int n_in,
                              void* d_out, int out_size)
{
    const float* pos = (const float*)d_in[0];
    const float* nf  = (const float*)d_in[1];
    const int*   snd = (const int*)d_in[2];
    const int*   rcv = (const int*)d_in[3];
    const float* Wss = (const float*)d_in[4];
    const float* Wsv = (const float*)d_in[5];
    const float* Wus = (const float*)d_in[6];
    const float* Wuv = (const float*)d_in[7];
    const float* W1  = (const float*)d_in[8];
    const float* W2  = (const float*)d_in[9];
    const float* W3  = (const float*)d_in[10];
    const float* Wds = (const float*)d_in[11];
    const float* Wdv = (const float*)d_in[12];
    float* out = (float*)d_out;

    pack_pos_kernel<<<NODE_BLOCKS, 256>>>(pos);
    geom_kernel<<<EDGE_BLOCKS, 256>>>(snd, rcv);
    {
        dim3 grid(TABLE_SIZE / 128, 3);
        table_kernel<<<grid, 128>>>(W1, W2, W3);
    }
    node_first_kernel<<<NODE_BLOCKS, 256>>>(nf, Wss, Wsv, Wus, Wuv);
    edge_kernel<<<EDGE_GRID, 256>>>(0);
    for (int l = 1; l < 3; ++l) {
        node_fused_kernel<<<NODE_BLOCKS, 256>>>(
            Wds + (l-1)*9, Wdv + (l-1)*10,
            Wss + l*3, Wsv + l*4, Wus + l, Wuv + l*4);
        edge_kernel<<<EDGE_GRID, 256>>>(l);
    }
    node_final_kernel<<<NODE_BLOCKS, 256>>>(Wds + 2*9, Wdv + 2*10, out);
}

// round 6
// speedup vs baseline: 1.4813x; 1.4813x over previous
#include <cuda_runtime.h>

#define N_NODES 50000
#define N_EDGES 1000000
#define TABLE_SIZE 8192

#define NODE_BLOCKS ((N_NODES + 255) / 256)
#define EDGE_BLOCKS ((N_EDGES + 255) / 256)
#define EDGE_GRID (148 * 8)   // grid-stride edge kernel

// ---------------- persistent scratch (no allocs allowed) ----------------
__device__ __align__(16) float4 g_pos4[N_NODES];        // packed positions
__device__ __align__(16) int2   g_edge[N_EDGES];        // {sender, receiver}
__device__ __align__(16) float4 g_nhat[N_EDGES];        // unit edge vector, .w = length
__device__ __align__(16) float  g_ssc[N_NODES * 3];     // self-connection scalar (layer l)
__device__ __align__(16) float  g_vsc[N_NODES * 6];     // self-connection vector (layer l)
__device__ __align__(16) float  g_usrc[N_NODES * 8];    // packed sender feats {vu[6], su, pad}
__device__ __align__(16) float  g_agg[N_NODES * 12];    // {sw[3], w0[3], w1[3], pad[3]}
__device__ __align__(16) float  g_table[3 * TABLE_SIZE * 8]; // mix_l(length) table

__device__ __forceinline__ float swishf(float x) {
    return __fdividef(x, 1.0f + __expf(-x));
}

// ---------------- K_pack: positions -> float4 ----------------
__global__ __launch_bounds__(256) void pack_pos_kernel(const float* __restrict__ pos)
{
    int n = blockIdx.x * 256 + threadIdx.x;
    if (n >= N_NODES) return;
    g_pos4[n] = make_float4(pos[3*n+0], pos[3*n+1], pos[3*n+2], 0.f);
}

// ---------------- K0: edge geometry + packed index (once per replay) ----------------
__global__ __launch_bounds__(256) void geom_kernel(
    const int* __restrict__ senders,
    const int* __restrict__ receivers)
{
    int e = blockIdx.x * 256 + threadIdx.x;
    if (e >= N_EDGES) return;
    int a = senders[e], b = receivers[e];
    g_edge[e] = make_int2(a, b);
    float4 pa = g_pos4[a];
    float4 pb = g_pos4[b];
    float dx = pb.x - pa.x;
    float dy = pb.y - pa.y;
    float dz = pb.z - pa.z;
    float len = sqrtf(dx*dx + dy*dy + dz*dz);
    float inv = (len > 0.f) ? (1.f / len) : 0.f;
    g_nhat[e] = make_float4(dx*inv, dy*inv, dz*inv, len);
}

// ---------------- K_tab: build mix(length) table, all 3 layers ----------------
__global__ __launch_bounds__(128) void table_kernel(
    const float* __restrict__ W1g, const float* __restrict__ W2g,
    const float* __restrict__ W3g)
{
    int l = blockIdx.y;
    const float* W1 = W1g + l * 512;
    const float* W2 = W2g + l * 4096;
    const float* W3 = W3g + l * 512;

    __shared__ float sW1[8*64];
    __shared__ float sW2[64*64];
    __shared__ float sW3[64*8];
    for (int i = threadIdx.x; i < 512; i += 128) { sW1[i] = W1[i]; sW3[i] = W3[i]; }
    for (int i = threadIdx.x; i < 4096; i += 128) sW2[i] = W2[i];
    __syncthreads();

    int idx = blockIdx.x * 128 + threadIdx.x;
    if (idx >= TABLE_SIZE) return;
    float x = (float)idx * (1.0f / (float)(TABLE_SIZE - 1));

    // radial basis at length x
    float x2 = x*x, x3 = x2*x, x6 = x3*x3, x7 = x6*x, x8 = x7*x;
    float poly = 1.f - 28.f*x6 + 48.f*x7 - 21.f*x8;
    float env = (x < 1.f) ? poly : 0.f;
    float inv = (x > 0.f) ? (1.f / x) : 0.f;
    float coef = 1.4142135623730951f * env * inv;
    float th = 3.14159265358979323846f * x;
    float s1, c1;
    sincosf(th, &s1, &c1);
    float c2 = 2.f * c1;
    float skm = 0.f, sk = s1;
    float rad[8];
#pragma unroll
    for (int k = 0; k < 8; ++k) {
        rad[k] = coef * sk;
        float sn = fmaf(c2, sk, -skm);
        skm = sk; sk = sn;
    }
    if (idx == 0) {
#pragma unroll
        for (int k = 0; k < 8; ++k) rad[k] = 0.f;  // len==0 edges skip anyway
    }

    // h = swish(radial @ W1 / sqrt(8))
    float h[64];
#pragma unroll
    for (int j = 0; j < 64; ++j) {
        float acc = 0.f;
#pragma unroll
        for (int i = 0; i < 8; ++i) acc = fmaf(rad[i], sW1[i*64 + j], acc);
        h[j] = swishf(acc * 0.35355339059327373f);
    }

    float mix[8];
#pragma unroll
    for (int k = 0; k < 8; ++k) mix[k] = 0.f;
#pragma unroll 1
    for (int jc = 0; jc < 64; jc += 16) {
        float g[16];
#pragma unroll
        for (int j = 0; j < 16; ++j) g[j] = 0.f;
#pragma unroll
        for (int i = 0; i < 64; ++i) {
            float hi = h[i];
            const float* w = &sW2[i*64 + jc];
#pragma unroll
            for (int j = 0; j < 16; ++j) g[j] = fmaf(hi, w[j], g[j]);
        }
#pragma unroll
        for (int j = 0; j < 16; ++j) {
            float gs = swishf(g[j] * 0.125f);
            const float* w3 = &sW3[(jc + j)*8];
#pragma unroll
            for (int k = 0; k < 8; ++k) mix[k] = fmaf(gs, w3[k], mix[k]);
        }
    }
    float4* T = (float4*)(g_table + ((size_t)l * TABLE_SIZE + idx) * 8);
    T[0] = make_float4(mix[0]*0.125f, mix[1]*0.125f, mix[2]*0.125f, mix[3]*0.125f);
    T[1] = make_float4(mix[4]*0.125f, mix[5]*0.125f, mix[6]*0.125f, mix[7]*0.125f);
}

// ---------------- per-node "pre" body (shared by fused kernels) ----------------
__device__ __forceinline__ void node_pre_body(
    int n, float s, const float* v,
    const float* __restrict__ Wss, const float* __restrict__ Wsv,
    const float* __restrict__ Wus, const float* __restrict__ Wuv)
{
    const float IS2 = 0.7071067811865476f;
#pragma unroll
    for (int j = 0; j < 3; ++j) g_ssc[n*3+j] = s * Wss[j];
#pragma unroll
    for (int k = 0; k < 2; ++k)
#pragma unroll
        for (int c = 0; c < 3; ++c)
            g_vsc[n*6 + k*3 + c] = (v[c]*Wsv[0*2+k] + v[3+c]*Wsv[1*2+k]) * IS2;

    float su = s * Wus[0];
    float vu[6];
#pragma unroll
    for (int k = 0; k < 2; ++k)
#pragma unroll
        for (int c = 0; c < 3; ++c)
            vu[k*3+c] = (v[c]*Wuv[0*2+k] + v[3+c]*Wuv[1*2+k]) * IS2;

    float4* u4 = (float4*)g_usrc;
    u4[2*n+0] = make_float4(vu[0], vu[1], vu[2], vu[3]);
    u4[2*n+1] = make_float4(vu[4], vu[5], su, 0.f);

    float4* ag4 = (float4*)(g_agg + (size_t)n*12);
#pragma unroll
    for (int i = 0; i < 3; ++i) ag4[i] = make_float4(0.f, 0.f, 0.f, 0.f);
}

// ---------------- per-node "post" body: agg+sc -> new (s, v) ----------------
// Wds/Wdv already folded into the scatter; only scale + add self-connection here.
__device__ __forceinline__ void node_post_body(
    int n, float& s_out, float* v_out)
{
    const float IS3 = 0.5773502691896258f;
    const float IS5 = 0.4472135954999579f;
    const float* base = g_agg + (size_t)n * 12;

    float st[3];
#pragma unroll
    for (int j = 0; j < 3; ++j)
        st[j] = base[j] * IS3 + g_ssc[n*3 + j];

    float vt[6];
#pragma unroll
    for (int k = 0; k < 2; ++k)
#pragma unroll
        for (int c = 0; c < 3; ++c)
            vt[k*3 + c] = base[3 + k*3 + c] * IS5 + g_vsc[n*6 + k*3 + c];

    s_out = swishf(st[0]);
    float a1 = swishf(st[1]);
    float a2 = swishf(st[2]);
#pragma unroll
    for (int c = 0; c < 3; ++c) {
        v_out[c]     = vt[c]     * a1;
        v_out[3 + c] = vt[3 + c] * a2;
    }
}

// ---------------- K1a: init from node_features + pre(0) ----------------
__global__ __launch_bounds__(256) void node_first_kernel(
    const float* __restrict__ nf,
    const float* __restrict__ Wss, const float* __restrict__ Wsv,
    const float* __restrict__ Wus, const float* __restrict__ Wuv)
{
    int n = blockIdx.x * 256 + threadIdx.x;
    if (n >= N_NODES) return;
    float s = nf[n*7];
    float v[6];
#pragma unroll
    for (int k = 0; k < 6; ++k) v[k] = nf[n*7 + 1 + k];
    node_pre_body(n, s, v, Wss, Wsv, Wus, Wuv);
}

// ---------------- K1b: post(l-1) fused with pre(l) ----------------
__global__ __launch_bounds__(256) void node_fused_kernel(
    const float* __restrict__ Wss, const float* __restrict__ Wsv,  // layer l
    const float* __restrict__ Wus, const float* __restrict__ Wuv)
{
    int n = blockIdx.x * 256 + threadIdx.x;
    if (n >= N_NODES) return;
    float s, v[6];
    node_post_body(n, s, v);
    node_pre_body(n, s, v, Wss, Wsv, Wus, Wuv);   // also zeros agg for layer l
}

// ---------------- K1c: final post (layer 2) -> out ----------------
__global__ __launch_bounds__(256) void node_final_kernel(float* __restrict__ out)
{
    int n = blockIdx.x * 256 + threadIdx.x;
    if (n >= N_NODES) return;
    float s, v[6];
    node_post_body(n, s, v);
#pragma unroll
    for (int c = 0; c < 3; ++c) out[n*3 + c] = v[c];
}

// ---------------- K2: per-edge table lookup + messages + folded scatter ----------------
__global__ __launch_bounds__(256) void edge_kernel(
    int layer,
    const float* __restrict__ WdsG, const float* __restrict__ WdvG)
{
    // layer weights for the folded contraction (broadcast loads, L1-resident)
    float wds[9], wdv[10];
#pragma unroll
    for (int i = 0; i < 9; ++i) wds[i] = __ldg(WdsG + i);
#pragma unroll
    for (int i = 0; i < 10; ++i) wdv[i] = __ldg(WdvG + i);

    const float4* Tbase = (const float4*)(g_table + (size_t)layer * TABLE_SIZE * 8);
    for (int e = blockIdx.x * 256 + threadIdx.x; e < N_EDGES; e += EDGE_GRID * 256) {
        float4 nh = g_nhat[e];
        float len = nh.w;
        // reference: radial==0 (=> mix==0 => all messages 0) for len==0 or len>=1
        if (len <= 0.f || len >= 1.f) continue;

        // mix(len) via table lerp
        float t = len * (float)(TABLE_SIZE - 1);
        int i0 = (int)t;
        if (i0 > TABLE_SIZE - 2) i0 = TABLE_SIZE - 2;
        float fr = t - (float)i0;
        const float4* T = Tbase + i0 * 2;
        float4 a0 = T[0], a1 = T[1], b0 = T[2], b1 = T[3];
        float m0 = fmaf(fr, b0.x - a0.x, a0.x);
        float m1 = fmaf(fr, b0.y - a0.y, a0.y);
        float m2 = fmaf(fr, b0.z - a0.z, a0.z);
        float m3 = fmaf(fr, b0.w - a0.w, a0.w);
        float m4 = fmaf(fr, b1.x - a1.x, a1.x);
        float m5 = fmaf(fr, b1.y - a1.y, a1.y);
        float m6 = fmaf(fr, b1.z - a1.z, a1.z);
        float m7 = fmaf(fr, b1.w - a1.w, a1.w);

        // gather sender features
        int2 ed = g_edge[e];
        int snd = ed.x, rcv = ed.y;
        const float4* u4 = (const float4*)g_usrc;
        float4 u0 = u4[2*snd+0], u1 = u4[2*snd+1];
        float v00 = u0.x, v01 = u0.y, v02 = u0.z;
        float v10 = u0.w, v11 = u1.x, v12 = u1.y;
        float se  = u1.z;
        float nx = nh.x, ny = nh.y, nz = nh.z;
        float vd0 = v00*nx + v01*ny + v02*nz;
        float vd1 = v10*nx + v11*ny + v12*nz;

        float f5 = 2.1213203435596424f * m5;
        float f6 = 2.1213203435596424f * m6;
        float f7 = 1.7320508075688772f * se * m7;

        // ---- fold Wds into scalar messages: sw[j] = sum_i msg_s[i]*Wds[i][j]
        float p0 = se * m0, p1 = vd0 * m1, p2 = vd1 * m2;
        float sw0 = p0*wds[0] + p1*wds[3] + p2*wds[6];
        float sw1 = p0*wds[1] + p1*wds[4] + p2*wds[7];
        float sw2 = p0*wds[2] + p1*wds[5] + p2*wds[8];

        // ---- fold Wdv into vector messages:
        // msg_v rows: r0=ve0*m3, r1=ve1*m4, pc0=f5*(vd0*n - ve0/3),
        //             pc1=f6*(vd1*n - ve1/3), pb=f7*n
        // w[k][c] = A_k*ve0[c] + B_k*ve1[c] + C_k*n[c]
        const float THIRD = 0.3333333333333333f;
        float A0 = m3*wdv[0] - f5*THIRD*wdv[4];
        float B0 = m4*wdv[2] - f6*THIRD*wdv[6];
        float C0 = f5*vd0*wdv[4] + f6*vd1*wdv[6] + f7*wdv[8];
        float A1 = m3*wdv[1] - f5*THIRD*wdv[5];
        float B1 = m4*wdv[3] - f6*THIRD*wdv[7];
        float C1 = f5*vd0*wdv[5] + f6*vd1*wdv[7] + f7*wdv[9];

        float w00 = A0*v00 + B0*v10 + C0*nx;
        float w01 = A0*v01 + B0*v11 + C0*ny;
        float w02 = A0*v02 + B0*v12 + C0*nz;
        float w10 = A1*v00 + B1*v10 + C1*nx;
        float w11 = A1*v01 + B1*v11 + C1*ny;
        float w12 = A1*v02 + B1*v12 + C1*nz;

        float* base = g_agg + (size_t)rcv * 12;
        atomicAdd((float4*)(base + 0), make_float4(sw0, sw1, sw2, w00));
        atomicAdd((float4*)(base + 4), make_float4(w01, w02, w10, w11));
        atomicAdd(base + 8, w12);
    }
}

// ---------------- launch ----------------
extern "C" void kernel_launch(void* const* d_in, const int* in_sizes, int n_in,
                              void* d_out, int out_size)
{
    const float* pos = (const float*)d_in[0];
    const float* nf  = (const float*)d_in[1];
    const int*   snd = (const int*)d_in[2];
    const int*   rcv = (const int*)d_in[3];
    const float* Wss = (const float*)d_in[4];
    const float* Wsv = (const float*)d_in[5];
    const float* Wus = (const float*)d_in[6];
    const float* Wuv = (const float*)d_in[7];
    const float* W1  = (const float*)d_in[8];
    const float* W2  = (const float*)d_in[9];
    const float* W3  = (const float*)d_in[10];
    const float* Wds = (const float*)d_in[11];
    const float* Wdv = (const float*)d_in[12];
    float* out = (float*)d_out;

    pack_pos_kernel<<<NODE_BLOCKS, 256>>>(pos);
    geom_kernel<<<EDGE_BLOCKS, 256>>>(snd, rcv);
    {
        dim3 grid(TABLE_SIZE / 128, 3);
        table_kernel<<<grid, 128>>>(W1, W2, W3);
    }
    node_first_kernel<<<NODE_BLOCKS, 256>>>(nf, Wss, Wsv, Wus, Wuv);
    edge_kernel<<<EDGE_GRID, 256>>>(0, Wds + 0*9, Wdv + 0*10);
    for (int l = 1; l < 3; ++l) {
        node_fused_kernel<<<NODE_BLOCKS, 256>>>(
            Wss + l*3, Wsv + l*4, Wus + l, Wuv + l*4);
        edge_kernel<<<EDGE_GRID, 256>>>(l, Wds + l*9, Wdv + l*10);
    }
    node_final_kernel<<<NODE_BLOCKS, 256>>>(out);
}